// round 5
// baseline (speedup 1.0000x reference)
#include <cuda_runtime.h>
#include <cstdint>

// ---------------------------------------------------------------------------
//   B=8, NK=NQ=2048, D=256, H=1024
//   All GEMMs NT: C[m,n] = alpha*sum_k A[m,k]*B[n,k] (+bias[n]), K-major A/B.
//   mma.sync.m16n8k8.tf32 + ldmatrix + cp.async multi-stage pipeline.
//   dist is computed TRANSPOSED (distT[k,i]) so softmax-over-k becomes a
//   column softmax and no 2048x2048 transpose pass is needed.
// ---------------------------------------------------------------------------

// ---- scratch (allocation forbidden -> device globals) ----
__device__ float g_rK[4194304];        // rounded KEY    [8,2048,256]
__device__ float g_rQ[4194304];
__device__ float g_rV[4194304];
__device__ float g_wk[262144];         // rounded weights [1024,256]
__device__ float g_wq[262144];
__device__ float g_wv[262144];
__device__ float g_wl[262144];         // rounded lin_w   [256,1024]
__device__ float g_Wk[16777216];       // projections [8,2048,1024]
__device__ float g_Wq[16777216];
__device__ float g_Wv[16777216];
__device__ float g_dist[33554432];     // distT [8][2048 k][2048 i]
__device__ float g_WvT[16777216];      // [8][1024 h][2048 i]
__device__ float g_ctx[16777216];      // [8][2048 k][1024 h]

// ---------------------------------------------------------------------------
__device__ __forceinline__ float rna_tf32(float x) {
    float r;
    asm("cvt.rna.tf32.f32 %0, %1;" : "=f"(r) : "f"(x));
    return r;
}
__device__ __forceinline__ uint32_t smem_u32(const void* p) {
    uint32_t a;
    asm("{ .reg .u64 t; cvta.to.shared.u64 t, %1; cvt.u32.u64 %0, t; }" : "=r"(a) : "l"(p));
    return a;
}
__device__ __forceinline__ void cp16(uint32_t dst, const void* src) {
    asm volatile("cp.async.cg.shared.global [%0], [%1], 16;" :: "r"(dst), "l"(src));
}
__device__ __forceinline__ void ldm4(uint32_t& a, uint32_t& b, uint32_t& c, uint32_t& d,
                                     uint32_t addr) {
    asm volatile("ldmatrix.sync.aligned.m8n8.x4.shared.b16 {%0,%1,%2,%3}, [%4];"
                 : "=r"(a), "=r"(b), "=r"(c), "=r"(d) : "r"(addr));
}
__device__ __forceinline__ void mma8(float* d, const uint32_t* a, const uint32_t* b) {
    asm volatile(
        "mma.sync.aligned.m16n8k8.row.col.f32.tf32.tf32.f32 "
        "{%0,%1,%2,%3}, {%4,%5,%6,%7}, {%8,%9}, {%0,%1,%2,%3};"
        : "+f"(d[0]), "+f"(d[1]), "+f"(d[2]), "+f"(d[3])
        : "r"(a[0]), "r"(a[1]), "r"(a[2]), "r"(a[3]), "r"(b[0]), "r"(b[1]));
}

// ---------------------------------------------------------------------------
// GEMM: C tile 128 x BN per CTA, 8 warps (2m x 4n), warp tile 64 x BN/4.
// A: [M,K] row-major. B: [N,K] row-major. C: [M,ldc] row-major.
template<int BN, int NST, bool ROUND>
__global__ void __launch_bounds__(256, (BN == 128) ? 2 : 1)
gemm_tf32(const float* __restrict__ A, const float* __restrict__ B,
          float* __restrict__ C, const float* __restrict__ bias,
          int K, int ldc,
          long long sA, long long sB, long long sC, float alpha)
{
    constexpr int WN   = BN / 4;        // warp n-tile (64 or 32)
    constexpr int NT8  = WN / 8;        // n8-subtiles per warp (8 or 4)
    constexpr int NG   = WN / 16;       // B ldm4 groups per ks (4 or 2)
    constexpr int ROWS = 128 + BN;      // smem rows per stage (A then B)
    constexpr int STAGE = ROWS * 128;   // bytes per stage
    constexpr int CPT  = ROWS / 32;     // cp16 per thread per stage

    extern __shared__ char smem[];
    const int tid = threadIdx.x;
    const int lane = tid & 31;
    const int wid = tid >> 5;
    const int m0 = blockIdx.y * 128;
    const int n0 = blockIdx.x * BN;
    const int wm = (wid >> 2) * 64;
    const int wn = (wid & 3) * WN;

    const float* Ab = A + (long long)blockIdx.z * sA + (long long)m0 * K;
    const float* Bb = B + (long long)blockIdx.z * sB + (long long)n0 * K;
    float*       Cb = C + (long long)blockIdx.z * sC;

    const uint32_t sbase = smem_u32(smem);

    // cp.async per-thread pattern
    const int r0row = tid >> 3;                         // 0..31
    const int seg   = tid & 7;                          // 16B segment
    const uint32_t swoff = (uint32_t)(seg * 16) ^ (uint32_t)((r0row & 7) << 4);

    // ldmatrix lane addressing (swizzled K-major tiles, 128B pitch)
    const uint32_t xorv = (uint32_t)((lane & 7) << 4);
    const int laneA_row = ((lane >> 3) & 1) * 8 + (lane & 7);
    const uint32_t laneA_col = (uint32_t)((lane >> 4) * 16);
    const int laneB_row = (lane >> 4) * 8 + (lane & 7);
    const uint32_t laneB_col = (uint32_t)(((lane >> 3) & 1) * 16);

    float acc[4][NT8][4];
#pragma unroll
    for (int i = 0; i < 4; i++)
#pragma unroll
        for (int j = 0; j < NT8; j++)
#pragma unroll
            for (int e = 0; e < 4; e++)
                acc[i][j][e] = 0.0f;

    const int NC = K >> 5;

    // ---- prologue ----
#pragma unroll
    for (int s = 0; s < NST - 1; s++) {
        const uint32_t ds = sbase + s * STAGE;
        const int bk = s * 32;
#pragma unroll
        for (int i = 0; i < CPT; i++) {
            const int row = r0row + 32 * i;
            const float* src = (row < 128) ? (Ab + (long long)row * K)
                                           : (Bb + (long long)(row - 128) * K);
            cp16(ds + (uint32_t)(row * 128) + swoff, src + bk + seg * 4);
        }
        asm volatile("cp.async.commit_group;" ::: "memory");
    }

    // ---- main loop ----
    for (int j = 0; j < NC; j++) {
        asm volatile("cp.async.wait_group %0;" :: "n"(NST - 2) : "memory");
        __syncthreads();

        const int jf = j + NST - 1;
        if (jf < NC) {
            const uint32_t ds = sbase + (jf % NST) * STAGE;
            const int bk = jf * 32;
#pragma unroll
            for (int i = 0; i < CPT; i++) {
                const int row = r0row + 32 * i;
                const float* src = (row < 128) ? (Ab + (long long)row * K)
                                               : (Bb + (long long)(row - 128) * K);
                cp16(ds + (uint32_t)(row * 128) + swoff, src + bk + seg * 4);
            }
        }
        asm volatile("cp.async.commit_group;" ::: "memory");

        const uint32_t ta = sbase + (j % NST) * STAGE;
        const uint32_t tb = ta + 16384;
        const uint32_t baseA = ta + (uint32_t)((wm + laneA_row) * 128);
        const uint32_t baseB = tb + (uint32_t)((wn + laneB_row) * 128);

#pragma unroll
        for (int ks = 0; ks < 4; ks++) {
            const uint32_t kb = (uint32_t)(ks * 32);
            uint32_t af[4][4];
            uint32_t bf[NG][4];
#pragma unroll
            for (int mt = 0; mt < 4; mt++)
                ldm4(af[mt][0], af[mt][1], af[mt][2], af[mt][3],
                     baseA + (uint32_t)(mt * 16 * 128) + ((kb + laneA_col) ^ xorv));
#pragma unroll
            for (int g = 0; g < NG; g++)
                ldm4(bf[g][0], bf[g][1], bf[g][2], bf[g][3],
                     baseB + (uint32_t)(g * 16 * 128) + ((kb + laneB_col) ^ xorv));
#pragma unroll
            for (int mt = 0; mt < 4; mt++)
#pragma unroll
                for (int nt = 0; nt < NT8; nt++)
                    mma8(acc[mt][nt], af[mt], &bf[nt >> 1][(nt & 1) * 2]);
        }
    }

    // ---- epilogue ----
    const int erow = lane >> 2;
    const int ecol = (lane & 3) * 2;
#pragma unroll
    for (int mt = 0; mt < 4; mt++) {
#pragma unroll
        for (int nt = 0; nt < NT8; nt++) {
            const int gm = m0 + wm + mt * 16 + erow;
            const int gn = n0 + wn + nt * 8 + ecol;
            float b0 = 0.0f, b1 = 0.0f;
            if (bias) { b0 = __ldg(bias + gn); b1 = __ldg(bias + gn + 1); }
            float2 v0, v1;
            v0.x = acc[mt][nt][0] * alpha + b0;
            v0.y = acc[mt][nt][1] * alpha + b1;
            v1.x = acc[mt][nt][2] * alpha + b0;
            v1.y = acc[mt][nt][3] * alpha + b1;
            if (ROUND) {
                v0.x = rna_tf32(v0.x); v0.y = rna_tf32(v0.y);
                v1.x = rna_tf32(v1.x); v1.y = rna_tf32(v1.y);
            }
            *(float2*)(Cb + (long long)gm * ldc + gn) = v0;
            *(float2*)(Cb + (long long)(gm + 8) * ldc + gn) = v1;
        }
    }
}

// ---------------------------------------------------------------------------
// Merged rna->tf32 rounding copies (cuts launch count).
__global__ void __launch_bounds__(256)
round3(const float4* __restrict__ a, const float4* __restrict__ b,
       const float4* __restrict__ c,
       float4* __restrict__ oa, float4* __restrict__ ob, float4* __restrict__ oc,
       int n4)
{
    for (int i = blockIdx.x * blockDim.x + threadIdx.x; i < n4;
         i += gridDim.x * blockDim.x) {
        float4 va = a[i], vb = b[i], vc = c[i];
        va.x = rna_tf32(va.x); va.y = rna_tf32(va.y); va.z = rna_tf32(va.z); va.w = rna_tf32(va.w);
        vb.x = rna_tf32(vb.x); vb.y = rna_tf32(vb.y); vb.z = rna_tf32(vb.z); vb.w = rna_tf32(vb.w);
        vc.x = rna_tf32(vc.x); vc.y = rna_tf32(vc.y); vc.z = rna_tf32(vc.z); vc.w = rna_tf32(vc.w);
        oa[i] = va; ob[i] = vb; oc[i] = vc;
    }
}
__global__ void __launch_bounds__(256)
round4(const float4* __restrict__ a, const float4* __restrict__ b,
       const float4* __restrict__ c, const float4* __restrict__ d,
       float4* __restrict__ oa, float4* __restrict__ ob,
       float4* __restrict__ oc, float4* __restrict__ od, int n4)
{
    for (int i = blockIdx.x * blockDim.x + threadIdx.x; i < n4;
         i += gridDim.x * blockDim.x) {
        float4 va = a[i], vb = b[i], vc = c[i], vd = d[i];
        va.x = rna_tf32(va.x); va.y = rna_tf32(va.y); va.z = rna_tf32(va.z); va.w = rna_tf32(va.w);
        vb.x = rna_tf32(vb.x); vb.y = rna_tf32(vb.y); vb.z = rna_tf32(vb.z); vb.w = rna_tf32(vb.w);
        vc.x = rna_tf32(vc.x); vc.y = rna_tf32(vc.y); vc.z = rna_tf32(vc.z); vc.w = rna_tf32(vc.w);
        vd.x = rna_tf32(vd.x); vd.y = rna_tf32(vd.y); vd.z = rna_tf32(vd.z); vd.w = rna_tf32(vd.w);
        oa[i] = va; ob[i] = vb; oc[i] = vc; od[i] = vd;
    }
}

// ---------------------------------------------------------------------------
// Column softmax on distT [2048 rows k][2048 cols i] per batch.
// Each block: strip of 16 columns, all 2048 rows, smem-resident (128KB).
// Output rounded to tf32 (feeds ctx GEMM's A operand).
__global__ void __launch_bounds__(256)
colsoftmax(float* __restrict__ data)
{
    extern __shared__ float s[];                 // 2048*16 floats
    __shared__ float red[256];
    __shared__ float mz[32];                     // m[16], inv-sum[16]

    const int tid = threadIdx.x;
    float* p = data + (long long)blockIdx.y * (2048LL * 2048) + blockIdx.x * 16;
    const int c4 = tid & 3;

    // load strip
#pragma unroll 4
    for (int it = 0; it < 32; it++) {
        const int row = (tid >> 2) + 64 * it;
        float4 v = *(const float4*)(p + (long long)row * 2048 + c4 * 4);
        *(float4*)(s + row * 16 + c4 * 4) = v;
    }
    __syncthreads();

    // per-column max (col = tid&15, row groups tid>>4 + 16j)
    const int col = tid & 15, rg = tid >> 4;
    float m = -3.0e38f;
#pragma unroll 8
    for (int jj = 0; jj < 128; jj++) m = fmaxf(m, s[(rg + 16 * jj) * 16 + col]);
    red[tid] = m; __syncthreads();
    if (tid < 16) {
        float mm = red[tid];
#pragma unroll
        for (int g = 1; g < 16; g++) mm = fmaxf(mm, red[tid + 16 * g]);
        mz[tid] = mm;
    }
    __syncthreads();
    m = mz[col];

    // exp in place + per-column sum
    float sum = 0.0f;
#pragma unroll 8
    for (int jj = 0; jj < 128; jj++) {
        const int idx = (rg + 16 * jj) * 16 + col;
        const float e = __expf(s[idx] - m);
        s[idx] = e;
        sum += e;
    }
    red[tid] = sum; __syncthreads();
    if (tid < 16) {
        float ss = 0.0f;
#pragma unroll
        for (int g = 0; g < 16; g++) ss += red[tid + 16 * g];
        mz[16 + tid] = 1.0f / ss;
    }
    __syncthreads();

    // scaled, rounded write-back
#pragma unroll 4
    for (int it = 0; it < 32; it++) {
        const int row = (tid >> 2) + 64 * it;
        float4 v = *(float4*)(s + row * 16 + c4 * 4);
        float4 o;
        o.x = rna_tf32(v.x * mz[16 + c4 * 4 + 0]);
        o.y = rna_tf32(v.y * mz[16 + c4 * 4 + 1]);
        o.z = rna_tf32(v.z * mz[16 + c4 * 4 + 2]);
        o.w = rna_tf32(v.w * mz[16 + c4 * 4 + 3]);
        *(float4*)(p + (long long)row * 2048 + c4 * 4) = o;
    }
}

// ---------------------------------------------------------------------------
// Batched tiled transpose: in [R,Cc] -> out [Cc,R] per batch (bit-exact).
__global__ void __launch_bounds__(256)
transpose_b(const float* __restrict__ in, float* __restrict__ out, int R, int Cc)
{
    __shared__ float t[32][33];
    const long long bo = (long long)blockIdx.z * R * Cc;
    const float* ib = in + bo;
    float* ob = out + bo;
    const int c0 = blockIdx.x * 32, r0 = blockIdx.y * 32;
    const int lx = threadIdx.x & 31, ly = threadIdx.x >> 5;
#pragma unroll
    for (int rr = 0; rr < 32; rr += 8)
        t[ly + rr][lx] = ib[(long long)(r0 + ly + rr) * Cc + c0 + lx];
    __syncthreads();
#pragma unroll
    for (int rr = 0; rr < 32; rr += 8)
        ob[(long long)(c0 + ly + rr) * R + r0 + lx] = t[lx][ly + rr];
}

// ---------------------------------------------------------------------------
extern "C" void kernel_launch(void* const* d_in, const int* in_sizes, int n_in,
                              void* d_out, int out_size)
{
    const float* KEY   = (const float*)d_in[0];
    const float* VALUE = (const float*)d_in[1];
    const float* QUERY = (const float*)d_in[2];
    const float* Wk_w  = (const float*)d_in[3];
    const float* Wk_b  = (const float*)d_in[4];
    const float* Wq_w  = (const float*)d_in[5];
    const float* Wq_b  = (const float*)d_in[6];
    const float* Wv_w  = (const float*)d_in[7];
    const float* Wv_b  = (const float*)d_in[8];
    const float* lin_w = (const float*)d_in[9];
    const float* lin_b = (const float*)d_in[10];
    float* out = (float*)d_out;

    float *rK, *rQ, *rV, *wk, *wq, *wv, *wl;
    float *pWk, *pWq, *pWv, *pD, *pVT, *pC;
    cudaGetSymbolAddress((void**)&rK, g_rK);
    cudaGetSymbolAddress((void**)&rQ, g_rQ);
    cudaGetSymbolAddress((void**)&rV, g_rV);
    cudaGetSymbolAddress((void**)&wk, g_wk);
    cudaGetSymbolAddress((void**)&wq, g_wq);
    cudaGetSymbolAddress((void**)&wv, g_wv);
    cudaGetSymbolAddress((void**)&wl, g_wl);
    cudaGetSymbolAddress((void**)&pWk, g_Wk);
    cudaGetSymbolAddress((void**)&pWq, g_Wq);
    cudaGetSymbolAddress((void**)&pWv, g_Wv);
    cudaGetSymbolAddress((void**)&pD,  g_dist);
    cudaGetSymbolAddress((void**)&pVT, g_WvT);
    cudaGetSymbolAddress((void**)&pC,  g_ctx);

    constexpr int SM_BIG   = 3 * (128 + 256) * 128;   // 147456
    constexpr int SM_SMALL = 3 * (128 + 128) * 128;   // 98304
    cudaFuncSetAttribute(gemm_tf32<256, 3, true>,
                         cudaFuncAttributeMaxDynamicSharedMemorySize, SM_BIG);
    cudaFuncSetAttribute(gemm_tf32<256, 3, false>,
                         cudaFuncAttributeMaxDynamicSharedMemorySize, SM_BIG);
    cudaFuncSetAttribute(gemm_tf32<128, 3, false>,
                         cudaFuncAttributeMaxDynamicSharedMemorySize, SM_SMALL);
    cudaFuncSetAttribute(colsoftmax,
                         cudaFuncAttributeMaxDynamicSharedMemorySize, 131072);

    dim3 blk(256);

    // round inputs + weights to tf32 (rna): every MMA operand pre-rounded
    round3<<<1024, blk>>>((const float4*)KEY, (const float4*)QUERY, (const float4*)VALUE,
                          (float4*)rK, (float4*)rQ, (float4*)rV, 4194304 / 4);
    round4<<<512, blk>>>((const float4*)Wk_w, (const float4*)Wq_w,
                         (const float4*)Wv_w, (const float4*)lin_w,
                         (float4*)wk, (float4*)wq, (float4*)wv, (float4*)wl, 262144 / 4);

    // projections: M=16384, N=1024, K=256
    gemm_tf32<256, 3, true><<<dim3(4, 128, 1), blk, SM_BIG>>>(
        rK, wk, pWk, Wk_b, 256, 1024, 0, 0, 0, 1.0f);
    gemm_tf32<256, 3, true><<<dim3(4, 128, 1), blk, SM_BIG>>>(
        rQ, wq, pWq, Wq_b, 256, 1024, 0, 0, 0, 1.0f);
    gemm_tf32<256, 3, true><<<dim3(4, 128, 1), blk, SM_BIG>>>(
        rV, wv, pWv, Wv_b, 256, 1024, 0, 0, 0, 1.0f);

    // distT[k,i] = Wq[k,:].Wk[i,:]/32 : M=N=2048, K=1024, batched over 8
    gemm_tf32<256, 3, false><<<dim3(8, 16, 8), blk, SM_BIG>>>(
        pWq, pWk, pD, nullptr, 1024, 2048,
        2048LL * 1024, 2048LL * 1024, 2048LL * 2048, 0.03125f);

    // softmax over k (rows of distT) per column i, in place, tf32-rounded out
    colsoftmax<<<dim3(128, 8), blk, 131072>>>(pD);

    // Wv [i,h] -> WvT [h,i]
    transpose_b<<<dim3(32, 64, 8), blk>>>(pWv, pVT, 2048, 1024);

    // ctx[k,h] = sum_i w'[k,i] * WvT[h,i] : M=2048, N=1024, K=2048, batched
    gemm_tf32<256, 3, true><<<dim3(4, 16, 8), blk, SM_BIG>>>(
        pD, pVT, pC, nullptr, 2048, 1024,
        2048LL * 2048, 2048LL * 1024, 2048LL * 1024, 1.0f);

    // out = ctx @ lin_w.T + lin_b : M=16384, N=256, K=1024
    gemm_tf32<128, 3, false><<<dim3(2, 128, 1), blk, SM_SMALL>>>(
        pC, wl, out, lin_b, 1024, 256, 0, 0, 0, 1.0f);
}

// round 7
// speedup vs baseline: 1.0739x; 1.0739x over previous
#include <cuda_runtime.h>
#include <cstdint>

// ---------------------------------------------------------------------------
//   B=8, NK=NQ=2048, D=256, H=1024
//   All GEMMs NT: C[m,n] = alpha*sum_k A[m,k]*B[n,k] (+bias[n]), K-major A/B.
//   mma.sync.m16n8k8.tf32 + ldmatrix + cp.async 3-stage pipeline (256 thr,
//   2 CTA/SM — the R3-validated config).
//   dist computed TRANSPOSED (distT[k,i]) -> softmax-over-k is a column
//   softmax on contiguous strips; no 2048x2048 transpose (R5-validated).
// ---------------------------------------------------------------------------

#define NSTAGE 3
#define STAGE_BYTES 32768              // A 16KB + B 16KB
#define DYN_SMEM (NSTAGE * STAGE_BYTES)

// ---- scratch (allocation forbidden -> device globals) ----
__device__ float g_rK[4194304];        // rounded KEY    [8,2048,256]
__device__ float g_rQ[4194304];
__device__ float g_rV[4194304];
__device__ float g_wk[262144];         // rounded weights [1024,256]
__device__ float g_wq[262144];
__device__ float g_wv[262144];
__device__ float g_wl[262144];         // rounded lin_w   [256,1024]
__device__ float g_Wk[16777216];       // projections [8,2048,1024]
__device__ float g_Wq[16777216];
__device__ float g_Wv[16777216];
__device__ float g_dist[33554432];     // distT [8][2048 k][2048 i]
__device__ float g_WvT[16777216];      // [8][1024 h][2048 i]
__device__ float g_ctx[16777216];      // [8][2048 k][1024 h]

// ---------------------------------------------------------------------------
__device__ __forceinline__ float rna_tf32(float x) {
    float r;
    asm("cvt.rna.tf32.f32 %0, %1;" : "=f"(r) : "f"(x));
    return r;
}
__device__ __forceinline__ uint32_t smem_u32(const void* p) {
    uint32_t a;
    asm("{ .reg .u64 t; cvta.to.shared.u64 t, %1; cvt.u32.u64 %0, t; }" : "=r"(a) : "l"(p));
    return a;
}
__device__ __forceinline__ void cp16(uint32_t dst, const void* src) {
    asm volatile("cp.async.cg.shared.global [%0], [%1], 16;" :: "r"(dst), "l"(src));
}
__device__ __forceinline__ void ldm4(uint32_t& a, uint32_t& b, uint32_t& c, uint32_t& d,
                                     uint32_t addr) {
    asm volatile("ldmatrix.sync.aligned.m8n8.x4.shared.b16 {%0,%1,%2,%3}, [%4];"
                 : "=r"(a), "=r"(b), "=r"(c), "=r"(d) : "r"(addr));
}
__device__ __forceinline__ void mma8(float* d, const uint32_t* a, const uint32_t* b) {
    asm volatile(
        "mma.sync.aligned.m16n8k8.row.col.f32.tf32.tf32.f32 "
        "{%0,%1,%2,%3}, {%4,%5,%6,%7}, {%8,%9}, {%0,%1,%2,%3};"
        : "+f"(d[0]), "+f"(d[1]), "+f"(d[2]), "+f"(d[3])
        : "r"(a[0]), "r"(a[1]), "r"(a[2]), "r"(a[3]), "r"(b[0]), "r"(b[1]));
}

// ---------------------------------------------------------------------------
// C tile 128x128 per CTA. 8 warps (2m x 4n), warp tile 64x32. (R3 config.)
// A: [M,K] row-major. B: [N,K] row-major. C: [M,ldc] row-major.
template<bool ROUND>
__global__ void __launch_bounds__(256, 2)
gemm_tf32(const float* __restrict__ A, const float* __restrict__ B,
          float* __restrict__ C, const float* __restrict__ bias,
          int K, int ldc,
          long long sA, long long sB, long long sC, float alpha)
{
    extern __shared__ char smem[];
    const int tid = threadIdx.x;
    const int lane = tid & 31;
    const int wid = tid >> 5;
    const int m0 = blockIdx.y * 128;
    const int n0 = blockIdx.x * 128;
    const int wm = (wid >> 2) * 64;    // 0 or 64
    const int wn = (wid & 3) * 32;     // 0,32,64,96

    const float* Ab = A + (long long)blockIdx.z * sA + (long long)m0 * K;
    const float* Bb = B + (long long)blockIdx.z * sB + (long long)n0 * K;
    float*       Cb = C + (long long)blockIdx.z * sC;

    const uint32_t sbase = smem_u32(smem);

    // cp.async per-thread pattern: 4 rounds per operand per stage
    const int r0row = tid >> 3;                         // 0..31
    const int seg   = tid & 7;                          // 16B segment
    const uint32_t swoff = (uint32_t)(seg * 16) ^ (uint32_t)((r0row & 7) << 4);

    // ldmatrix per-lane addressing (swizzled K-major tiles, 128B rows)
    const uint32_t xorv = (uint32_t)((lane & 7) << 4);
    const int laneA_row = ((lane >> 3) & 1) * 8 + (lane & 7);
    const uint32_t laneA_col = (uint32_t)((lane >> 4) * 16);
    const int laneB_row = (lane >> 4) * 8 + (lane & 7);
    const uint32_t laneB_col = (uint32_t)(((lane >> 3) & 1) * 16);

    float acc[4][4][4];
#pragma unroll
    for (int i = 0; i < 4; i++)
#pragma unroll
        for (int j = 0; j < 4; j++)
#pragma unroll
            for (int e = 0; e < 4; e++)
                acc[i][j][e] = 0.0f;

    const int NC = K >> 5;   // 32-wide K chunks

    // ---- prologue: stages 0,1 ----
#pragma unroll
    for (int s = 0; s < NSTAGE - 1; s++) {
        const uint32_t da = sbase + s * STAGE_BYTES;
        const uint32_t db = da + 16384;
        const int bk = s * 32;
#pragma unroll
        for (int i = 0; i < 4; i++) {
            const int row = r0row + 32 * i;
            cp16(da + (uint32_t)(row * 128) + swoff, Ab + (long long)row * K + bk + seg * 4);
            cp16(db + (uint32_t)(row * 128) + swoff, Bb + (long long)row * K + bk + seg * 4);
        }
        asm volatile("cp.async.commit_group;" ::: "memory");
    }

    // ---- main loop ----
    for (int j = 0; j < NC; j++) {
        asm volatile("cp.async.wait_group %0;" :: "n"(NSTAGE - 2) : "memory");
        __syncthreads();

        // issue stage j+2
        const int jf = j + NSTAGE - 1;
        if (jf < NC) {
            const uint32_t da = sbase + (jf % NSTAGE) * STAGE_BYTES;
            const uint32_t db = da + 16384;
            const int bk = jf * 32;
#pragma unroll
            for (int i = 0; i < 4; i++) {
                const int row = r0row + 32 * i;
                cp16(da + (uint32_t)(row * 128) + swoff, Ab + (long long)row * K + bk + seg * 4);
                cp16(db + (uint32_t)(row * 128) + swoff, Bb + (long long)row * K + bk + seg * 4);
            }
        }
        asm volatile("cp.async.commit_group;" ::: "memory");

        // compute on stage j
        const uint32_t ta = sbase + (j % NSTAGE) * STAGE_BYTES;
        const uint32_t tb = ta + 16384;
        const uint32_t baseA = ta + (uint32_t)((wm + laneA_row) * 128);
        const uint32_t baseB = tb + (uint32_t)((wn + laneB_row) * 128);

#pragma unroll
        for (int ks = 0; ks < 4; ks++) {
            const uint32_t kb = (uint32_t)(ks * 32);   // kk*4 bytes
            uint32_t af[4][4];
            uint32_t bf[2][4];
#pragma unroll
            for (int mt = 0; mt < 4; mt++)
                ldm4(af[mt][0], af[mt][1], af[mt][2], af[mt][3],
                     baseA + (uint32_t)(mt * 16 * 128) + ((kb + laneA_col) ^ xorv));
#pragma unroll
            for (int nt2 = 0; nt2 < 2; nt2++)
                ldm4(bf[nt2][0], bf[nt2][1], bf[nt2][2], bf[nt2][3],
                     baseB + (uint32_t)(nt2 * 16 * 128) + ((kb + laneB_col) ^ xorv));
#pragma unroll
            for (int mt = 0; mt < 4; mt++)
#pragma unroll
                for (int nt = 0; nt < 4; nt++)
                    mma8(acc[mt][nt], af[mt], &bf[nt >> 1][(nt & 1) * 2]);
        }
    }

    // ---- epilogue: direct float2 stores, alpha + bias (+ tf32 rounding) ----
    const int erow = lane >> 2;
    const int ecol = (lane & 3) * 2;
#pragma unroll
    for (int mt = 0; mt < 4; mt++) {
#pragma unroll
        for (int nt = 0; nt < 4; nt++) {
            const int gm = m0 + wm + mt * 16 + erow;
            const int gn = n0 + wn + nt * 8 + ecol;
            float b0 = 0.0f, b1 = 0.0f;
            if (bias) { b0 = __ldg(bias + gn); b1 = __ldg(bias + gn + 1); }
            float2 v0, v1;
            v0.x = acc[mt][nt][0] * alpha + b0;
            v0.y = acc[mt][nt][1] * alpha + b1;
            v1.x = acc[mt][nt][2] * alpha + b0;
            v1.y = acc[mt][nt][3] * alpha + b1;
            if (ROUND) {
                v0.x = rna_tf32(v0.x); v0.y = rna_tf32(v0.y);
                v1.x = rna_tf32(v1.x); v1.y = rna_tf32(v1.y);
            }
            *(float2*)(Cb + (long long)gm * ldc + gn) = v0;
            *(float2*)(Cb + (long long)(gm + 8) * ldc + gn) = v1;
        }
    }
}

// ---------------------------------------------------------------------------
// Merged rna->tf32 rounding copies.
__global__ void __launch_bounds__(256)
round3(const float4* __restrict__ a, const float4* __restrict__ b,
       const float4* __restrict__ c,
       float4* __restrict__ oa, float4* __restrict__ ob, float4* __restrict__ oc,
       int n4)
{
    for (int i = blockIdx.x * blockDim.x + threadIdx.x; i < n4;
         i += gridDim.x * blockDim.x) {
        float4 va = a[i], vb = b[i], vc = c[i];
        va.x = rna_tf32(va.x); va.y = rna_tf32(va.y); va.z = rna_tf32(va.z); va.w = rna_tf32(va.w);
        vb.x = rna_tf32(vb.x); vb.y = rna_tf32(vb.y); vb.z = rna_tf32(vb.z); vb.w = rna_tf32(vb.w);
        vc.x = rna_tf32(vc.x); vc.y = rna_tf32(vc.y); vc.z = rna_tf32(vc.z); vc.w = rna_tf32(vc.w);
        oa[i] = va; ob[i] = vb; oc[i] = vc;
    }
}
__global__ void __launch_bounds__(256)
round4(const float4* __restrict__ a, const float4* __restrict__ b,
       const float4* __restrict__ c, const float4* __restrict__ d,
       float4* __restrict__ oa, float4* __restrict__ ob,
       float4* __restrict__ oc, float4* __restrict__ od, int n4)
{
    for (int i = blockIdx.x * blockDim.x + threadIdx.x; i < n4;
         i += gridDim.x * blockDim.x) {
        float4 va = a[i], vb = b[i], vc = c[i], vd = d[i];
        va.x = rna_tf32(va.x); va.y = rna_tf32(va.y); va.z = rna_tf32(va.z); va.w = rna_tf32(va.w);
        vb.x = rna_tf32(vb.x); vb.y = rna_tf32(vb.y); vb.z = rna_tf32(vb.z); vb.w = rna_tf32(vb.w);
        vc.x = rna_tf32(vc.x); vc.y = rna_tf32(vc.y); vc.z = rna_tf32(vc.z); vc.w = rna_tf32(vc.w);
        vd.x = rna_tf32(vd.x); vd.y = rna_tf32(vd.y); vd.z = rna_tf32(vd.z); vd.w = rna_tf32(vd.w);
        oa[i] = va; ob[i] = vb; oc[i] = vc; od[i] = vd;
    }
}

// ---------------------------------------------------------------------------
// Column softmax on distT [2048 rows k][2048 cols i] per batch.
// Each block: strip of 16 columns, all rows, smem-resident (128KB). (R5 cfg.)
__global__ void __launch_bounds__(256)
colsoftmax(float* __restrict__ data)
{
    extern __shared__ float s[];                 // 2048*16 floats
    __shared__ float red[256];
    __shared__ float mz[32];                     // m[16], inv-sum[16]

    const int tid = threadIdx.x;
    float* p = data + (long long)blockIdx.y * (2048LL * 2048) + blockIdx.x * 16;
    const int c4 = tid & 3;

#pragma unroll 4
    for (int it = 0; it < 32; it++) {
        const int row = (tid >> 2) + 64 * it;
        float4 v = *(const float4*)(p + (long long)row * 2048 + c4 * 4);
        *(float4*)(s + row * 16 + c4 * 4) = v;
    }
    __syncthreads();

    const int col = tid & 15, rg = tid >> 4;
    float m = -3.0e38f;
#pragma unroll 8
    for (int jj = 0; jj < 128; jj++) m = fmaxf(m, s[(rg + 16 * jj) * 16 + col]);
    red[tid] = m; __syncthreads();
    if (tid < 16) {
        float mm = red[tid];
#pragma unroll
        for (int g = 1; g < 16; g++) mm = fmaxf(mm, red[tid + 16 * g]);
        mz[tid] = mm;
    }
    __syncthreads();
    m = mz[col];

    float sum = 0.0f;
#pragma unroll 8
    for (int jj = 0; jj < 128; jj++) {
        const int idx = (rg + 16 * jj) * 16 + col;
        const float e = __expf(s[idx] - m);
        s[idx] = e;
        sum += e;
    }
    red[tid] = sum; __syncthreads();
    if (tid < 16) {
        float ss = 0.0f;
#pragma unroll
        for (int g = 0; g < 16; g++) ss += red[tid + 16 * g];
        mz[16 + tid] = 1.0f / ss;
    }
    __syncthreads();

#pragma unroll 4
    for (int it = 0; it < 32; it++) {
        const int row = (tid >> 2) + 64 * it;
        float4 v = *(float4*)(s + row * 16 + c4 * 4);
        float4 o;
        o.x = rna_tf32(v.x * mz[16 + c4 * 4 + 0]);
        o.y = rna_tf32(v.y * mz[16 + c4 * 4 + 1]);
        o.z = rna_tf32(v.z * mz[16 + c4 * 4 + 2]);
        o.w = rna_tf32(v.w * mz[16 + c4 * 4 + 3]);
        *(float4*)(p + (long long)row * 2048 + c4 * 4) = o;
    }
}

// ---------------------------------------------------------------------------
// Batched tiled transpose: in [R,Cc] -> out [Cc,R] per batch (bit-exact).
__global__ void __launch_bounds__(256)
transpose_b(const float* __restrict__ in, float* __restrict__ out, int R, int Cc)
{
    __shared__ float t[32][33];
    const long long bo = (long long)blockIdx.z * R * Cc;
    const float* ib = in + bo;
    float* ob = out + bo;
    const int c0 = blockIdx.x * 32, r0 = blockIdx.y * 32;
    const int lx = threadIdx.x & 31, ly = threadIdx.x >> 5;
#pragma unroll
    for (int rr = 0; rr < 32; rr += 8)
        t[ly + rr][lx] = ib[(long long)(r0 + ly + rr) * Cc + c0 + lx];
    __syncthreads();
#pragma unroll
    for (int rr = 0; rr < 32; rr += 8)
        ob[(long long)(c0 + ly + rr) * R + r0 + lx] = t[lx][ly + rr];
}

// ---------------------------------------------------------------------------
extern "C" void kernel_launch(void* const* d_in, const int* in_sizes, int n_in,
                              void* d_out, int out_size)
{
    const float* KEY   = (const float*)d_in[0];
    const float* VALUE = (const float*)d_in[1];
    const float* QUERY = (const float*)d_in[2];
    const float* Wk_w  = (const float*)d_in[3];
    const float* Wk_b  = (const float*)d_in[4];
    const float* Wq_w  = (const float*)d_in[5];
    const float* Wq_b  = (const float*)d_in[6];
    const float* Wv_w  = (const float*)d_in[7];
    const float* Wv_b  = (const float*)d_in[8];
    const float* lin_w = (const float*)d_in[9];
    const float* lin_b = (const float*)d_in[10];
    float* out = (float*)d_out;

    float *rK, *rQ, *rV, *wk, *wq, *wv, *wl;
    float *pWk, *pWq, *pWv, *pD, *pVT, *pC;
    cudaGetSymbolAddress((void**)&rK, g_rK);
    cudaGetSymbolAddress((void**)&rQ, g_rQ);
    cudaGetSymbolAddress((void**)&rV, g_rV);
    cudaGetSymbolAddress((void**)&wk, g_wk);
    cudaGetSymbolAddress((void**)&wq, g_wq);
    cudaGetSymbolAddress((void**)&wv, g_wv);
    cudaGetSymbolAddress((void**)&wl, g_wl);
    cudaGetSymbolAddress((void**)&pWk, g_Wk);
    cudaGetSymbolAddress((void**)&pWq, g_Wq);
    cudaGetSymbolAddress((void**)&pWv, g_Wv);
    cudaGetSymbolAddress((void**)&pD,  g_dist);
    cudaGetSymbolAddress((void**)&pVT, g_WvT);
    cudaGetSymbolAddress((void**)&pC,  g_ctx);

    cudaFuncSetAttribute(gemm_tf32<true>,  cudaFuncAttributeMaxDynamicSharedMemorySize, DYN_SMEM);
    cudaFuncSetAttribute(gemm_tf32<false>, cudaFuncAttributeMaxDynamicSharedMemorySize, DYN_SMEM);
    cudaFuncSetAttribute(colsoftmax,       cudaFuncAttributeMaxDynamicSharedMemorySize, 131072);

    dim3 blk(256);

    // round inputs + weights to tf32 (rna): every MMA operand pre-rounded
    round3<<<1024, blk>>>((const float4*)KEY, (const float4*)QUERY, (const float4*)VALUE,
                          (float4*)rK, (float4*)rQ, (float4*)rV, 4194304 / 4);
    round4<<<512, blk>>>((const float4*)Wk_w, (const float4*)Wq_w,
                         (const float4*)Wv_w, (const float4*)lin_w,
                         (float4*)wk, (float4*)wq, (float4*)wv, (float4*)wl, 262144 / 4);

    // projections: M=16384, N=1024, K=256
    gemm_tf32<true><<<dim3(8, 128, 1), blk, DYN_SMEM>>>(rK, wk, pWk, Wk_b, 256, 1024, 0, 0, 0, 1.0f);
    gemm_tf32<true><<<dim3(8, 128, 1), blk, DYN_SMEM>>>(rQ, wq, pWq, Wq_b, 256, 1024, 0, 0, 0, 1.0f);
    gemm_tf32<true><<<dim3(8, 128, 1), blk, DYN_SMEM>>>(rV, wv, pWv, Wv_b, 256, 1024, 0, 0, 0, 1.0f);

    // distT[k,i] = Wq[k,:].Wk[i,:]/32 : M=N=2048, K=1024, batched over 8
    gemm_tf32<false><<<dim3(16, 16, 8), blk, DYN_SMEM>>>(pWq, pWk, pD, nullptr, 1024, 2048,
        2048LL * 1024, 2048LL * 1024, 2048LL * 2048, 0.03125f);

    // softmax over k (rows of distT) per column i, in place, tf32-rounded out
    colsoftmax<<<dim3(128, 8), blk, 131072>>>(pD);

    // Wv [i,h] -> WvT [h,i]
    transpose_b<<<dim3(32, 64, 8), blk>>>(pWv, pVT, 2048, 1024);

    // ctx[k,h] = sum_i w'[k,i] * WvT[h,i] : M=2048, N=1024, K=2048, batched
    gemm_tf32<true><<<dim3(8, 16, 8), blk, DYN_SMEM>>>(pD, pVT, pC, nullptr, 2048, 1024,
        2048LL * 2048, 2048LL * 1024, 2048LL * 1024, 1.0f);

    // out = ctx @ lin_w.T + lin_b : M=16384, N=256, K=1024
    gemm_tf32<false><<<dim3(2, 128, 1), blk, DYN_SMEM>>>(pC, wl, out, lin_b, 1024, 256, 0, 0, 0, 1.0f);
}